// round 15
// baseline (speedup 1.0000x reference)
#include <cuda_runtime.h>
#include <cuda_fp16.h>
#include <cstdint>
#include <math.h>

#define BSZ    1024
#define DIM    128
#define NC     100000
#define NCH    782          // ceil(NC/128) class chunks of 128
#define SCALE  30.0f
#define MARGIN 0.35f

// ---------------- scratch ---------------------------------------------------
__device__ float    g_fn[BSZ * DIM];     // exact normalized input (for segment mean)
__device__ __half   g_fnr[BSZ * DIM];    // fp16-RNE fn (GEMM A operand)
__device__ __half   g_wr[NC * DIM];      // fp16-RNE weight (GEMM B operand)
__device__ float    g_invwn[NC];
__device__ float    g_pos[BSZ];
__device__ float    g_pm[BSZ * NCH];
__device__ float    g_ps[BSZ * NCH];
__device__ float    g_sums[NC * DIM];
__device__ float    g_counts[NC];
__device__ double   g_lossb[BSZ];
__device__ int      g_lab[BSZ];
__device__ int      g_is32;

// ---------------- helpers ----------------------------------------------------
__device__ __forceinline__ void mma16(float* c, const uint32_t* a, const uint32_t* b) {
    asm volatile(
        "mma.sync.aligned.m16n8k16.row.col.f32.f16.f16.f32 "
        "{%0,%1,%2,%3}, {%4,%5,%6,%7}, {%8,%9}, {%0,%1,%2,%3};"
        : "+f"(c[0]), "+f"(c[1]), "+f"(c[2]), "+f"(c[3])
        : "r"(a[0]), "r"(a[1]), "r"(a[2]), "r"(a[3]), "r"(b[0]), "r"(b[1]));
}
#define LDSM4(r0, r1, r2, r3, addr) \
    asm volatile("ldmatrix.sync.aligned.m8n8.x4.shared.b16 {%0,%1,%2,%3}, [%4];" \
        : "=r"(r0), "=r"(r1), "=r"(r2), "=r"(r3) : "r"(addr))
__device__ __forceinline__ uint32_t smem_u32(const void* p) {
    uint32_t a;
    asm("{ .reg .u64 t; cvta.to.shared.u64 t, %1; cvt.u32.u64 %0, t; }" : "=r"(a) : "l"(p));
    return a;
}
__device__ __forceinline__ uint32_t h2bits(float x, float y) {
    __half2 h = __floats2half2_rn(x, y);
    return *(uint32_t*)&h;
}
#define CP16(dst, src) asm volatile("cp.async.cg.shared.global [%0], [%1], 16;" :: "r"(dst), "l"(src) : "memory")
#define CP_COMMIT()    asm volatile("cp.async.commit_group;" ::: "memory")
#define CP_WAIT(n)     asm volatile("cp.async.wait_group %0;" :: "n"(n) : "memory")

// ---------------- kernel 0a/0b: label dtype detect + decode ----------------
__global__ void k_detect(const int* __restrict__ p) {
    int v = p[2 * threadIdx.x + 1];
    int any = __syncthreads_or(v != 0);
    if (threadIdx.x == 0) g_is32 = any ? 1 : 0;
}
__global__ void k_cvt(const int* __restrict__ p) {
    int b = blockIdx.x * 256 + threadIdx.x;
    if (b < BSZ) {
        int lab = p[g_is32 ? b : 2 * b];
        if (lab < 0) lab = 0;
        if (lab >= NC) lab = NC - 1;
        g_lab[b] = lab;
    }
}

// ---------------- kernel 1: normalize fn (exact + fp16 copies) -------------
__global__ void k_norm_fn(const float* __restrict__ in) {
    int row  = blockIdx.x * 8 + (threadIdx.x >> 5);
    int lane = threadIdx.x & 31;
    float4 v = ((const float4*)(in + row * DIM))[lane];
    float ss = v.x * v.x + v.y * v.y + v.z * v.z + v.w * v.w;
    #pragma unroll
    for (int o = 16; o; o >>= 1) ss += __shfl_xor_sync(0xffffffffu, ss, o);
    float inv = 1.0f / fmaxf(sqrtf(ss), 1e-12f);
    float4 r = make_float4(v.x * inv, v.y * inv, v.z * inv, v.w * inv);
    ((float4*)g_fn)[row * 32 + lane] = r;
    uint2 u = make_uint2(h2bits(r.x, r.y), h2bits(r.z, r.w));
    ((uint2*)g_fnr)[row * 32 + lane] = u;
}

// ---------------- kernel 2: inverse weight norms + fp16 weight copy --------
__global__ void k_invwn(const float* __restrict__ w) {
    int warp = blockIdx.x * 8 + (threadIdx.x >> 5);   // 6250 blocks * 8 warps
    int lane = threadIdx.x & 31;
    int r0 = warp * 2, r1 = r0 + 1;
    float4 v0 = ((const float4*)(w + (size_t)r0 * DIM))[lane];
    float4 v1 = ((const float4*)(w + (size_t)r1 * DIM))[lane];
    float s0 = v0.x*v0.x + v0.y*v0.y + v0.z*v0.z + v0.w*v0.w;
    float s1 = v1.x*v1.x + v1.y*v1.y + v1.z*v1.z + v1.w*v1.w;
    ((uint2*)g_wr)[(size_t)r0 * 32 + lane] = make_uint2(h2bits(v0.x, v0.y), h2bits(v0.z, v0.w));
    ((uint2*)g_wr)[(size_t)r1 * 32 + lane] = make_uint2(h2bits(v1.x, v1.y), h2bits(v1.z, v1.w));
    #pragma unroll
    for (int o = 16; o; o >>= 1) {
        s0 += __shfl_xor_sync(0xffffffffu, s0, o);
        s1 += __shfl_xor_sync(0xffffffffu, s1, o);
    }
    if (lane == 0) {
        g_invwn[r0] = 1.0f / fmaxf(sqrtf(s0), 1e-12f);
        g_invwn[r1] = 1.0f / fmaxf(sqrtf(s1), 1e-12f);
    }
}

// ---------------- kernel 3: zero counts / touched sum rows / pos -----------
__global__ void k_zero_counts() {
    int i = blockIdx.x * blockDim.x + threadIdx.x;
    if (i < NC)  g_counts[i] = 0.0f;
    if (i < BSZ) g_pos[i] = 0.0f;
}
__global__ void k_zero_sums() {
    int lab = g_lab[blockIdx.x];
    g_sums[(size_t)lab * DIM + threadIdx.x] = 0.0f;
}

// ---------------- kernel 4: fp16 mma + ldmatrix GEMM + fused softmax -------
// grid (NCH, 8). 256 thr, 2 CTAs/SM. Block tile 128x128, K=128 in 2 chunks of
// 64 halves, 2-stage double buffer. Fragment loads via ldmatrix.x4 (6 instrs
// per k-step vs 24 scalar LDS). Layout identical to the proven scalar map.
#define P36   36                      // smem pitch (u32) -> 144 B rows
#define STG   (128 * P36 * 4)         // one matrix, one stage: 18432 B
#define STAGE (2 * STG)               // A+B per stage: 36864 B
#define OFF_INVS (2 * STAGE)          // 73728
#define OFF_LABS (OFF_INVS + 512)
#define SMEM_SZ  (OFF_LABS + 512)

__global__ void __launch_bounds__(256, 2)
k_gemm() {
    extern __shared__ char smem[];
    const uint32_t sb = smem_u32(smem);
    float* invs = (float*)(smem + OFF_INVS);
    int*   labs = (int*)(smem + OFF_LABS);
    float* red  = (float*)smem;                  // overlay stage0 after MMA

    const int tid  = threadIdx.x;
    const int w    = tid >> 5, lane = tid & 31;
    const int q    = lane >> 2, qt = lane & 3;
    const int wm   = w >> 2, wn = w & 3;         // 2 x 4 warp grid
    const int c0   = blockIdx.x * 128;           // class chunk (fast dim)
    const int b0   = blockIdx.y * 128;           // batch tile

    if (tid < 128) {
        int c = c0 + tid;
        invs[tid] = (c < NC) ? g_invwn[c] * SCALE : 0.0f;
        labs[tid] = g_lab[b0 + tid];
    }

    // ---- prefetch one K-chunk of 64 halves (128 B/row = 8 x CP16) ----------
    auto prefetch = [&](int kc, int st) {
        uint32_t ao = sb + st * STAGE;
        uint32_t bo = ao + STG;
        #pragma unroll
        for (int it = 0; it < 4; it++) {
            int j = it * 256 + tid;
            int r = j >> 3, g = j & 7;
            CP16(ao + r * 144 + g * 16,
                 (const void*)(g_fnr + (size_t)(b0 + r) * DIM + kc * 64 + g * 8));
        }
        #pragma unroll
        for (int it = 0; it < 4; it++) {
            int j = it * 256 + tid;
            int r = j >> 3, g = j & 7;
            int c = c0 + r;
            if (c > NC - 1) c = NC - 1;          // clamp: finite, masked later
            CP16(bo + r * 144 + g * 16,
                 (const void*)(g_wr + (size_t)c * DIM + kc * 64 + g * 8));
        }
        CP_COMMIT();
    };

    float acc[4][4][4];
    #pragma unroll
    for (int i = 0; i < 4; i++)
        #pragma unroll
        for (int j = 0; j < 4; j++)
            #pragma unroll
            for (int x = 0; x < 4; x++) acc[i][j][x] = 0.0f;

    prefetch(0, 0);
    prefetch(1, 1);

    // per-lane ldmatrix row addressing (constant across chunks/steps):
    // A x4: lanes 0-7 -> (m0-7, kb0), 8-15 -> (m8-15, kb0),
    //       16-23 -> (m0-7, kb1), 24-31 -> (m8-15, kb1)
    const uint32_t a_off = (uint32_t)(wm * 64 + (lane & 15)) * 144 + (lane >> 4) * 16;
    // B x4 (two j-tiles per instr): lanes 0-7 -> (tile 2p, kb0), 8-15 -> (2p, kb1),
    //       16-23 -> (2p+1, kb0), 24-31 -> (2p+1, kb1)
    const uint32_t b_off = (uint32_t)(wn * 32 + (lane & 7) + ((lane >> 4) << 3)) * 144
                         + ((lane >> 3) & 1) * 16;

    #pragma unroll
    for (int ch = 0; ch < 2; ch++) {
        if (ch == 0) CP_WAIT(1); else CP_WAIT(0);
        __syncthreads();
        const uint32_t a_base = sb + ch * STAGE + a_off;
        const uint32_t b_base = sb + ch * STAGE + STG + b_off;
        #pragma unroll
        for (int s = 0; s < 4; s++) {            // 4 k16-steps per chunk
            uint32_t a[4][4], b[4][2];
            #pragma unroll
            for (int i = 0; i < 4; i++)
                LDSM4(a[i][0], a[i][1], a[i][2], a[i][3],
                      a_base + i * 16 * 144 + s * 32);
            #pragma unroll
            for (int p = 0; p < 2; p++)
                LDSM4(b[2 * p][0], b[2 * p][1], b[2 * p + 1][0], b[2 * p + 1][1],
                      b_base + p * 16 * 144 + s * 32);
            #pragma unroll
            for (int i = 0; i < 4; i++)
                #pragma unroll
                for (int j = 0; j < 4; j++)
                    mma16(acc[i][j], a[i], b[j]);
        }
    }
    __syncthreads();   // all MMA smem reads done; safe to overlay reduction bufs

    // ---- epilogue: quad-shuffle row reduce, then 4-warp SMEM combine ----
    float* red_m = red;          // [128][4]
    float* red_s = red + 512;    // [128][4]
    #pragma unroll
    for (int i = 0; i < 4; i++) {
        #pragma unroll
        for (int h = 0; h < 2; h++) {
            int rloc = wm * 64 + i * 16 + q + h * 8;
            int lab  = labs[rloc];
            float vals[8];
            int   cols[8];
            float m = -INFINITY;
            #pragma unroll
            for (int j = 0; j < 4; j++) {
                #pragma unroll
                for (int cc = 0; cc < 2; cc++) {
                    int cl = wn * 32 + j * 8 + 2 * qt + cc;
                    int c  = c0 + cl;
                    float v = acc[i][j][h * 2 + cc] * invs[cl];
                    vals[j * 2 + cc] = v;
                    cols[j * 2 + cc] = c;
                    if (c == lab) g_pos[b0 + rloc] = v;   // exactly one writer
                    if (c < NC && c != lab) m = fmaxf(m, v);
                }
            }
            m = fmaxf(m, __shfl_xor_sync(0xffffffffu, m, 1));
            m = fmaxf(m, __shfl_xor_sync(0xffffffffu, m, 2));
            float ssum = 0.0f;
            #pragma unroll
            for (int x = 0; x < 8; x++)
                if (cols[x] < NC && cols[x] != lab) ssum += __expf(vals[x] - m);
            ssum += __shfl_xor_sync(0xffffffffu, ssum, 1);
            ssum += __shfl_xor_sync(0xffffffffu, ssum, 2);
            if (qt == 0) {
                red_m[rloc * 4 + wn] = m;
                red_s[rloc * 4 + wn] = ssum;
            }
        }
    }
    __syncthreads();
    if (tid < 128) {
        float M = red_m[tid * 4], S = red_s[tid * 4];
        #pragma unroll
        for (int x = 1; x < 4; x++) {
            float m2 = red_m[tid * 4 + x], s2 = red_s[tid * 4 + x];
            if (m2 > M)      { S = S * __expf(M - m2) + s2; M = m2; }
            else if (s2 > 0) { S += s2 * __expf(m2 - M); }
        }
        size_t pi = (size_t)(b0 + tid) * NCH + blockIdx.x;
        g_pm[pi] = M;
        g_ps[pi] = S;
    }
}

// ---------------- kernel 5: per-row logsumexp combine + softplus -----------
__global__ void k_lossrow() {
    const int b = blockIdx.x;
    const int t = threadIdx.x;
    float M = -INFINITY, L = 0.0f;
    for (int ch = t; ch < NCH; ch += 256) {
        float m = g_pm[(size_t)b * NCH + ch];
        float s = g_ps[(size_t)b * NCH + ch];
        if (s > 0.0f) {
            if (m > M) { L = L * expf(M - m) + s; M = m; }
            else       { L += s * expf(m - M); }
        }
    }
    __shared__ float sm[256], ss[256];
    sm[t] = M; ss[t] = L;
    __syncthreads();
    for (int st = 128; st; st >>= 1) {
        if (t < st) {
            float m2 = sm[t + st], s2 = ss[t + st];
            float M1 = sm[t],      L1 = ss[t];
            if (s2 > 0.0f) {
                if (m2 > M1) { L1 = L1 * expf(M1 - m2) + s2; M1 = m2; }
                else         { L1 += s2 * expf(m2 - M1); }
            }
            sm[t] = M1; ss[t] = L1;
        }
        __syncthreads();
    }
    if (t == 0) {
        double lse = (double)sm[0] + log((double)ss[0]);
        double x = (double)MARGIN + lse - (double)g_pos[b];
        g_lossb[b] = (x > 0.0) ? (x + log1p(exp(-x))) : log1p(exp(x));
    }
}

// ---------------- kernel 6: deterministic mean -----------------------------
__global__ void k_losssum(float* __restrict__ out) {
    __shared__ double sm[1024];
    int t = threadIdx.x;
    sm[t] = g_lossb[t];
    __syncthreads();
    for (int st = 512; st; st >>= 1) {
        if (t < st) sm[t] += sm[t + st];
        __syncthreads();
    }
    if (t == 0) out[0] = (float)(sm[0] * (1.0 / 1024.0));
}

// ---------------- kernel 7/8: segment scatter + final blend ----------------
__global__ void k_accum() {
    int b   = blockIdx.x;
    int lab = g_lab[b];
    atomicAdd(&g_sums[(size_t)lab * DIM + threadIdx.x], g_fn[b * DIM + threadIdx.x]);
    if (threadIdx.x == 0) atomicAdd(&g_counts[lab], 1.0f);
}
__global__ void k_final(const float* __restrict__ weight, float* __restrict__ out) {
    size_t i = (size_t)blockIdx.x * 256 + threadIdx.x;
    int c = (int)(i >> 7);
    float cnt = g_counts[c];       // warp-uniform branch: one load path per warp
    float r;
    if (cnt > 0.0f) r = g_sums[i] / cnt;
    else            r = weight[i];
    out[1 + i] = r;
}

// ---------------- launch ---------------------------------------------------
extern "C" void kernel_launch(void* const* d_in, const int* in_sizes, int n_in,
                              void* d_out, int out_size) {
    const float* input  = nullptr;
    const int*   labraw = nullptr;
    const float* weight = nullptr;
    for (int i = 0; i < n_in; i++) {
        if      (in_sizes[i] == BSZ * DIM) input  = (const float*)d_in[i];
        else if (in_sizes[i] == BSZ)       labraw = (const int*)d_in[i];
        else if (in_sizes[i] == NC * DIM)  weight = (const float*)d_in[i];
    }
    float* out = (float*)d_out;

    cudaFuncSetAttribute(k_gemm, cudaFuncAttributeMaxDynamicSharedMemorySize, SMEM_SZ);

    k_detect     <<<1,     512>>>(labraw);
    k_cvt        <<<4,     256>>>(labraw);
    k_norm_fn    <<<128,   256>>>(input);
    k_invwn      <<<6250,  256>>>(weight);
    k_zero_counts<<<391,   256>>>();
    k_zero_sums  <<<1024,  128>>>();
    k_gemm       <<<dim3(NCH, 8), 256, SMEM_SZ>>>();
    k_lossrow    <<<1024,  256>>>();
    k_losssum    <<<1,    1024>>>(out);
    k_accum      <<<1024,  128>>>();
    k_final      <<<50000, 256>>>(weight, out);
}

// round 16
// speedup vs baseline: 1.0074x; 1.0074x over previous
#include <cuda_runtime.h>
#include <cuda_fp16.h>
#include <cstdint>
#include <math.h>

#define BSZ    1024
#define DIM    128
#define NC     100000
#define NCH    782          // ceil(NC/128) class chunks of 128
#define SCALE  30.0f
#define MARGIN 0.35f

// ---------------- scratch ---------------------------------------------------
__device__ float    g_fn[BSZ * DIM];     // exact normalized input (for segment mean)
__device__ __half   g_fnr[BSZ * DIM];    // fp16-RNE fn (GEMM A operand)
__device__ __half   g_wr[NC * DIM];      // fp16-RNE weight (GEMM B operand)
__device__ float    g_invwn[NC];
__device__ float    g_pos[BSZ];
__device__ float    g_pm[BSZ * NCH];
__device__ float    g_ps[BSZ * NCH];
__device__ float    g_sums[NC * DIM];
__device__ float    g_counts[NC];
__device__ double   g_lossb[BSZ];
__device__ int      g_lab[BSZ];
__device__ int      g_is32;

// ---------------- helpers ----------------------------------------------------
__device__ __forceinline__ void mma16(float* c, const uint32_t* a, const uint32_t* b) {
    asm volatile(
        "mma.sync.aligned.m16n8k16.row.col.f32.f16.f16.f32 "
        "{%0,%1,%2,%3}, {%4,%5,%6,%7}, {%8,%9}, {%0,%1,%2,%3};"
        : "+f"(c[0]), "+f"(c[1]), "+f"(c[2]), "+f"(c[3])
        : "r"(a[0]), "r"(a[1]), "r"(a[2]), "r"(a[3]), "r"(b[0]), "r"(b[1]));
}
__device__ __forceinline__ uint32_t smem_u32(const void* p) {
    uint32_t a;
    asm("{ .reg .u64 t; cvta.to.shared.u64 t, %1; cvt.u32.u64 %0, t; }" : "=r"(a) : "l"(p));
    return a;
}
__device__ __forceinline__ uint32_t h2bits(float x, float y) {
    __half2 h = __floats2half2_rn(x, y);
    return *(uint32_t*)&h;
}
#define CP16(dst, src) asm volatile("cp.async.cg.shared.global [%0], [%1], 16;" :: "r"(dst), "l"(src) : "memory")
#define CP_COMMIT()    asm volatile("cp.async.commit_group;" ::: "memory")
#define CP_WAIT(n)     asm volatile("cp.async.wait_group %0;" :: "n"(n) : "memory")

// ---------------- kernel 0a/0b: label dtype detect + decode ----------------
__global__ void k_detect(const int* __restrict__ p) {
    int v = p[2 * threadIdx.x + 1];
    int any = __syncthreads_or(v != 0);
    if (threadIdx.x == 0) g_is32 = any ? 1 : 0;
}
__global__ void k_cvt(const int* __restrict__ p) {
    int b = blockIdx.x * 256 + threadIdx.x;
    if (b < BSZ) {
        int lab = p[g_is32 ? b : 2 * b];
        if (lab < 0) lab = 0;
        if (lab >= NC) lab = NC - 1;
        g_lab[b] = lab;
    }
}

// ---------------- kernel 1: normalize fn (exact + fp16 copies) -------------
__global__ void k_norm_fn(const float* __restrict__ in) {
    int row  = blockIdx.x * 8 + (threadIdx.x >> 5);
    int lane = threadIdx.x & 31;
    float4 v = ((const float4*)(in + row * DIM))[lane];
    float ss = v.x * v.x + v.y * v.y + v.z * v.z + v.w * v.w;
    #pragma unroll
    for (int o = 16; o; o >>= 1) ss += __shfl_xor_sync(0xffffffffu, ss, o);
    float inv = 1.0f / fmaxf(sqrtf(ss), 1e-12f);
    float4 r = make_float4(v.x * inv, v.y * inv, v.z * inv, v.w * inv);
    ((float4*)g_fn)[row * 32 + lane] = r;
    uint2 u = make_uint2(h2bits(r.x, r.y), h2bits(r.z, r.w));
    ((uint2*)g_fnr)[row * 32 + lane] = u;
}

// ---------------- kernel 2: inverse weight norms + fp16 weight copy --------
__global__ void k_invwn(const float* __restrict__ w) {
    int warp = blockIdx.x * 8 + (threadIdx.x >> 5);   // 6250 blocks * 8 warps
    int lane = threadIdx.x & 31;
    int r0 = warp * 2, r1 = r0 + 1;
    float4 v0 = ((const float4*)(w + (size_t)r0 * DIM))[lane];
    float4 v1 = ((const float4*)(w + (size_t)r1 * DIM))[lane];
    float s0 = v0.x*v0.x + v0.y*v0.y + v0.z*v0.z + v0.w*v0.w;
    float s1 = v1.x*v1.x + v1.y*v1.y + v1.z*v1.z + v1.w*v1.w;
    ((uint2*)g_wr)[(size_t)r0 * 32 + lane] = make_uint2(h2bits(v0.x, v0.y), h2bits(v0.z, v0.w));
    ((uint2*)g_wr)[(size_t)r1 * 32 + lane] = make_uint2(h2bits(v1.x, v1.y), h2bits(v1.z, v1.w));
    #pragma unroll
    for (int o = 16; o; o >>= 1) {
        s0 += __shfl_xor_sync(0xffffffffu, s0, o);
        s1 += __shfl_xor_sync(0xffffffffu, s1, o);
    }
    if (lane == 0) {
        g_invwn[r0] = 1.0f / fmaxf(sqrtf(s0), 1e-12f);
        g_invwn[r1] = 1.0f / fmaxf(sqrtf(s1), 1e-12f);
    }
}

// ---------------- kernel 3: zero counts / touched sum rows / pos -----------
__global__ void k_zero_counts() {
    int i = blockIdx.x * blockDim.x + threadIdx.x;
    if (i < NC)  g_counts[i] = 0.0f;
    if (i < BSZ) g_pos[i] = 0.0f;
}
__global__ void k_zero_sums() {
    int lab = g_lab[blockIdx.x];
    g_sums[(size_t)lab * DIM + threadIdx.x] = 0.0f;
}

// ---------------- kernel 4: fp16 mma GEMM, B reused across 2 M-tiles -------
// grid (NCH, 4). Each CTA stages its 128-class B tile ONCE (both K-chunks,
// 36.9KB) and runs two 128-row M-tiles against it, reusing accumulators.
// A double-buffered per chunk; epilogue(t0) overlaps prefetch of A(t1).
// B DRAM traffic: 205 -> 102 MB. 256 thr, 2 CTAs/SM. Scalar fragment loads
// (ldmatrix measured slower in R15).
#define P36   36                      // smem pitch (u32) -> 144 B rows
#define STG   (128 * P36 * 4)         // one matrix chunk: 18432 B
#define OFF_B0   0
#define OFF_B1   STG
#define OFF_A0   (2 * STG)
#define OFF_A1   (3 * STG)
#define OFF_RED  (4 * STG)            // 4096 B (dedicated: B must stay live)
#define OFF_INVS (OFF_RED + 4096)
#define OFF_LABS (OFF_INVS + 512)
#define SMEM_SZ  (OFF_LABS + 1024)    // 79360 B; x2 CTAs = 158720 <= 228KB

__global__ void __launch_bounds__(256, 2)
k_gemm() {
    extern __shared__ char smem[];
    const uint32_t sb = smem_u32(smem);
    float* invs  = (float*)(smem + OFF_INVS);
    int*   labs  = (int*)(smem + OFF_LABS);    // 256 rows (both tiles)
    float* red_m = (float*)(smem + OFF_RED);   // [128][4]
    float* red_s = red_m + 512;

    const int tid  = threadIdx.x;
    const int w    = tid >> 5, lane = tid & 31;
    const int q    = lane >> 2, qt = lane & 3;
    const int wm   = w >> 2, wn = w & 3;       // 2 x 4 warp grid
    const int c0   = blockIdx.x * 128;         // class chunk (fast dim)
    const int B0   = blockIdx.y * 256;         // first batch row of this CTA

    {
        int c = c0 + tid;
        if (tid < 128) invs[tid] = (c < NC) ? g_invwn[c] * SCALE : 0.0f;
        labs[tid] = g_lab[B0 + tid];
    }

    // ---- B: both K-chunks, staged once ----
    auto prefetch_B = [&]() {
        #pragma unroll
        for (int kc = 0; kc < 2; kc++) {
            uint32_t bo = sb + (kc ? OFF_B1 : OFF_B0);
            #pragma unroll
            for (int it = 0; it < 4; it++) {
                int j = it * 256 + tid;
                int r = j >> 3, g = j & 7;
                int c = c0 + r;
                if (c > NC - 1) c = NC - 1;    // clamp: finite, masked later
                CP16(bo + r * 144 + g * 16,
                     (const void*)(g_wr + (size_t)c * DIM + kc * 64 + g * 8));
            }
        }
        CP_COMMIT();
    };
    // ---- A: one K-chunk of one M-tile ----
    auto prefetch_A = [&](int t, int kc, uint32_t off) {
        uint32_t ao = sb + off;
        int b0t = B0 + t * 128;
        #pragma unroll
        for (int it = 0; it < 4; it++) {
            int j = it * 256 + tid;
            int r = j >> 3, g = j & 7;
            CP16(ao + r * 144 + g * 16,
                 (const void*)(g_fnr + (size_t)(b0t + r) * DIM + kc * 64 + g * 8));
        }
        CP_COMMIT();
    };

    float acc[4][4][4];
    auto zero_acc = [&]() {
        #pragma unroll
        for (int i = 0; i < 4; i++)
            #pragma unroll
            for (int j = 0; j < 4; j++)
                #pragma unroll
                for (int x = 0; x < 4; x++) acc[i][j][x] = 0.0f;
    };

    auto mma_chunk = [&](uint32_t a_off, uint32_t b_off) {
        const uint32_t* As = (const uint32_t*)(smem + a_off);
        const uint32_t* Bs = (const uint32_t*)(smem + b_off);
        const uint32_t* Ab = &As[(wm * 64 + q) * P36 + qt];
        const uint32_t* Bb = &Bs[(wn * 32 + q) * P36 + qt];
        #pragma unroll
        for (int s = 0; s < 4; s++) {          // 4 k16-steps per chunk
            uint32_t a[4][4], b[4][2];
            #pragma unroll
            for (int i = 0; i < 4; i++) {
                const uint32_t* p = Ab + i * 16 * P36 + s * 8;
                a[i][0] = p[0];
                a[i][1] = p[8 * P36];
                a[i][2] = p[4];
                a[i][3] = p[8 * P36 + 4];
            }
            #pragma unroll
            for (int j = 0; j < 4; j++) {
                const uint32_t* p = Bb + j * 8 * P36 + s * 8;
                b[j][0] = p[0];
                b[j][1] = p[4];
            }
            #pragma unroll
            for (int i = 0; i < 4; i++)
                #pragma unroll
                for (int j = 0; j < 4; j++)
                    mma16(acc[i][j], a[i], b[j]);
        }
    };

    // epilogue for tile t: quad-shuffle row reduce, 4-warp SMEM combine
    auto epilogue = [&](int t) {
        const int b0t = B0 + t * 128;
        #pragma unroll
        for (int i = 0; i < 4; i++) {
            #pragma unroll
            for (int h = 0; h < 2; h++) {
                int rloc = wm * 64 + i * 16 + q + h * 8;
                int lab  = labs[t * 128 + rloc];
                float vals[8];
                int   cols[8];
                float m = -INFINITY;
                #pragma unroll
                for (int j = 0; j < 4; j++) {
                    #pragma unroll
                    for (int cc = 0; cc < 2; cc++) {
                        int cl = wn * 32 + j * 8 + 2 * qt + cc;
                        int c  = c0 + cl;
                        float v = acc[i][j][h * 2 + cc] * invs[cl];
                        vals[j * 2 + cc] = v;
                        cols[j * 2 + cc] = c;
                        if (c == lab) g_pos[b0t + rloc] = v;   // one writer
                        if (c < NC && c != lab) m = fmaxf(m, v);
                    }
                }
                m = fmaxf(m, __shfl_xor_sync(0xffffffffu, m, 1));
                m = fmaxf(m, __shfl_xor_sync(0xffffffffu, m, 2));
                float ssum = 0.0f;
                #pragma unroll
                for (int x = 0; x < 8; x++)
                    if (cols[x] < NC && cols[x] != lab) ssum += __expf(vals[x] - m);
                ssum += __shfl_xor_sync(0xffffffffu, ssum, 1);
                ssum += __shfl_xor_sync(0xffffffffu, ssum, 2);
                if (qt == 0) {
                    red_m[rloc * 4 + wn] = m;
                    red_s[rloc * 4 + wn] = ssum;
                }
            }
        }
        __syncthreads();
        if (tid < 128) {
            float M = red_m[tid * 4], S = red_s[tid * 4];
            #pragma unroll
            for (int x = 1; x < 4; x++) {
                float m2 = red_m[tid * 4 + x], s2 = red_s[tid * 4 + x];
                if (m2 > M)      { S = S * __expf(M - m2) + s2; M = m2; }
                else if (s2 > 0) { S += s2 * __expf(m2 - M); }
            }
            size_t pi = (size_t)(b0t + tid) * NCH + blockIdx.x;
            g_pm[pi] = M;
            g_ps[pi] = S;
        }
        __syncthreads();   // red reusable by next epilogue
    };

    // ---------------- tile 0 ----------------
    prefetch_B();                       // group 1
    prefetch_A(0, 0, OFF_A0);           // group 2
    prefetch_A(0, 1, OFF_A1);           // group 3
    zero_acc();
    CP_WAIT(1);                         // B + A(0,0) done
    __syncthreads();
    mma_chunk(OFF_A0, OFF_B0);
    CP_WAIT(0);                         // A(0,1) done
    __syncthreads();
    mma_chunk(OFF_A1, OFF_B1);
    __syncthreads();                    // all reads of A bufs complete

    // ---------------- tile 1 prefetch overlaps tile-0 epilogue -------------
    prefetch_A(1, 0, OFF_A0);           // group 4
    prefetch_A(1, 1, OFF_A1);           // group 5
    epilogue(0);
    zero_acc();
    CP_WAIT(0);
    __syncthreads();
    mma_chunk(OFF_A0, OFF_B0);
    mma_chunk(OFF_A1, OFF_B1);
    __syncthreads();
    epilogue(1);
}

// ---------------- kernel 5: per-row logsumexp combine + softplus -----------
__global__ void k_lossrow() {
    const int b = blockIdx.x;
    const int t = threadIdx.x;
    float M = -INFINITY, L = 0.0f;
    for (int ch = t; ch < NCH; ch += 256) {
        float m = g_pm[(size_t)b * NCH + ch];
        float s = g_ps[(size_t)b * NCH + ch];
        if (s > 0.0f) {
            if (m > M) { L = L * expf(M - m) + s; M = m; }
            else       { L += s * expf(m - M); }
        }
    }
    __shared__ float sm[256], ss[256];
    sm[t] = M; ss[t] = L;
    __syncthreads();
    for (int st = 128; st; st >>= 1) {
        if (t < st) {
            float m2 = sm[t + st], s2 = ss[t + st];
            float M1 = sm[t],      L1 = ss[t];
            if (s2 > 0.0f) {
                if (m2 > M1) { L1 = L1 * expf(M1 - m2) + s2; M1 = m2; }
                else         { L1 += s2 * expf(m2 - M1); }
            }
            sm[t] = M1; ss[t] = L1;
        }
        __syncthreads();
    }
    if (t == 0) {
        double lse = (double)sm[0] + log((double)ss[0]);
        double x = (double)MARGIN + lse - (double)g_pos[b];
        g_lossb[b] = (x > 0.0) ? (x + log1p(exp(-x))) : log1p(exp(x));
    }
}

// ---------------- kernel 6: deterministic mean -----------------------------
__global__ void k_losssum(float* __restrict__ out) {
    __shared__ double sm[1024];
    int t = threadIdx.x;
    sm[t] = g_lossb[t];
    __syncthreads();
    for (int st = 512; st; st >>= 1) {
        if (t < st) sm[t] += sm[t + st];
        __syncthreads();
    }
    if (t == 0) out[0] = (float)(sm[0] * (1.0 / 1024.0));
}

// ---------------- kernel 7/8: segment scatter + final blend ----------------
__global__ void k_accum() {
    int b   = blockIdx.x;
    int lab = g_lab[b];
    atomicAdd(&g_sums[(size_t)lab * DIM + threadIdx.x], g_fn[b * DIM + threadIdx.x]);
    if (threadIdx.x == 0) atomicAdd(&g_counts[lab], 1.0f);
}
__global__ void k_final(const float* __restrict__ weight, float* __restrict__ out) {
    size_t i = (size_t)blockIdx.x * 256 + threadIdx.x;
    int c = (int)(i >> 7);
    float cnt = g_counts[c];       // warp-uniform branch: one load path per warp
    float r;
    if (cnt > 0.0f) r = g_sums[i] / cnt;
    else            r = weight[i];
    out[1 + i] = r;
}

// ---------------- launch ---------------------------------------------------
extern "C" void kernel_launch(void* const* d_in, const int* in_sizes, int n_in,
                              void* d_out, int out_size) {
    const float* input  = nullptr;
    const int*   labraw = nullptr;
    const float* weight = nullptr;
    for (int i = 0; i < n_in; i++) {
        if      (in_sizes[i] == BSZ * DIM) input  = (const float*)d_in[i];
        else if (in_sizes[i] == BSZ)       labraw = (const int*)d_in[i];
        else if (in_sizes[i] == NC * DIM)  weight = (const float*)d_in[i];
    }
    float* out = (float*)d_out;

    cudaFuncSetAttribute(k_gemm, cudaFuncAttributeMaxDynamicSharedMemorySize, SMEM_SZ);

    k_detect     <<<1,     512>>>(labraw);
    k_cvt        <<<4,     256>>>(labraw);
    k_norm_fn    <<<128,   256>>>(input);
    k_invwn      <<<6250,  256>>>(weight);
    k_zero_counts<<<391,   256>>>();
    k_zero_sums  <<<1024,  128>>>();
    k_gemm       <<<dim3(NCH, 4), 256, SMEM_SZ>>>();
    k_lossrow    <<<1024,  256>>>();
    k_losssum    <<<1,    1024>>>(out);
    k_accum      <<<1024,  128>>>();
    k_final      <<<50000, 256>>>(weight, out);
}

// round 17
// speedup vs baseline: 1.0747x; 1.0667x over previous
#include <cuda_runtime.h>
#include <cuda_fp16.h>
#include <cstdint>
#include <math.h>

#define BSZ    1024
#define DIM    128
#define NC     100000
#define NCH    782          // ceil(NC/128) class chunks of 128
#define NTILES (NCH * 8)    // 6256
#define GRID   296          // 148 SMs x 2 CTAs: exactly one wave
#define SCALE  30.0f
#define MARGIN 0.35f

// ---------------- scratch ---------------------------------------------------
__device__ float    g_fn[BSZ * DIM];     // exact normalized input (for segment mean)
__device__ __half   g_fnr[BSZ * DIM];    // fp16-RNE fn (GEMM A operand)
__device__ __half   g_wr[NC * DIM];      // fp16-RNE weight (GEMM B operand)
__device__ float    g_invwn[NC];
__device__ float    g_pos[BSZ];
__device__ float    g_pm[BSZ * NCH];
__device__ float    g_ps[BSZ * NCH];
__device__ float    g_sums[NC * DIM];
__device__ float    g_counts[NC];
__device__ double   g_lossb[BSZ];
__device__ int      g_lab[BSZ];

// ---------------- helpers ----------------------------------------------------
__device__ __forceinline__ void mma16(float* c, const uint32_t* a, const uint32_t* b) {
    asm volatile(
        "mma.sync.aligned.m16n8k16.row.col.f32.f16.f16.f32 "
        "{%0,%1,%2,%3}, {%4,%5,%6,%7}, {%8,%9}, {%0,%1,%2,%3};"
        : "+f"(c[0]), "+f"(c[1]), "+f"(c[2]), "+f"(c[3])
        : "r"(a[0]), "r"(a[1]), "r"(a[2]), "r"(a[3]), "r"(b[0]), "r"(b[1]));
}
__device__ __forceinline__ uint32_t smem_u32(const void* p) {
    uint32_t a;
    asm("{ .reg .u64 t; cvta.to.shared.u64 t, %1; cvt.u32.u64 %0, t; }" : "=r"(a) : "l"(p));
    return a;
}
__device__ __forceinline__ uint32_t h2bits(float x, float y) {
    __half2 h = __floats2half2_rn(x, y);
    return *(uint32_t*)&h;
}
#define CP16(dst, src) asm volatile("cp.async.cg.shared.global [%0], [%1], 16;" :: "r"(dst), "l"(src) : "memory")
#define CP_COMMIT()    asm volatile("cp.async.commit_group;" ::: "memory")
#define CP_WAIT(n)     asm volatile("cp.async.wait_group %0;" :: "n"(n) : "memory")

// ---------------- kernel 0: label dtype detect + decode (one block) --------
__global__ void k_cvt(const int* __restrict__ p) {
    int t = threadIdx.x;                 // 1024 threads
    int v = (t < 512) ? p[2 * t + 1] : 0;
    int any = __syncthreads_or(v != 0);  // int32 labels -> odd words nonzero
    int lab = p[any ? t : 2 * t];
    if (lab < 0) lab = 0;
    if (lab >= NC) lab = NC - 1;
    g_lab[t] = lab;
}

// ---------------- kernel 1: normalize fn (exact + fp16 copies) -------------
__global__ void k_norm_fn(const float* __restrict__ in) {
    int row  = blockIdx.x * 8 + (threadIdx.x >> 5);
    int lane = threadIdx.x & 31;
    float4 v = ((const float4*)(in + row * DIM))[lane];
    float ss = v.x * v.x + v.y * v.y + v.z * v.z + v.w * v.w;
    #pragma unroll
    for (int o = 16; o; o >>= 1) ss += __shfl_xor_sync(0xffffffffu, ss, o);
    float inv = 1.0f / fmaxf(sqrtf(ss), 1e-12f);
    float4 r = make_float4(v.x * inv, v.y * inv, v.z * inv, v.w * inv);
    ((float4*)g_fn)[row * 32 + lane] = r;
    uint2 u = make_uint2(h2bits(r.x, r.y), h2bits(r.z, r.w));
    ((uint2*)g_fnr)[row * 32 + lane] = u;
}

// ---------------- kernel 2: inverse weight norms + fp16 weight copy --------
__global__ void k_invwn(const float* __restrict__ w) {
    int warp = blockIdx.x * 8 + (threadIdx.x >> 5);   // 6250 blocks * 8 warps
    int lane = threadIdx.x & 31;
    int r0 = warp * 2, r1 = r0 + 1;
    float4 v0 = ((const float4*)(w + (size_t)r0 * DIM))[lane];
    float4 v1 = ((const float4*)(w + (size_t)r1 * DIM))[lane];
    float s0 = v0.x*v0.x + v0.y*v0.y + v0.z*v0.z + v0.w*v0.w;
    float s1 = v1.x*v1.x + v1.y*v1.y + v1.z*v1.z + v1.w*v1.w;
    ((uint2*)g_wr)[(size_t)r0 * 32 + lane] = make_uint2(h2bits(v0.x, v0.y), h2bits(v0.z, v0.w));
    ((uint2*)g_wr)[(size_t)r1 * 32 + lane] = make_uint2(h2bits(v1.x, v1.y), h2bits(v1.z, v1.w));
    #pragma unroll
    for (int o = 16; o; o >>= 1) {
        s0 += __shfl_xor_sync(0xffffffffu, s0, o);
        s1 += __shfl_xor_sync(0xffffffffu, s1, o);
    }
    if (lane == 0) {
        g_invwn[r0] = 1.0f / fmaxf(sqrtf(s0), 1e-12f);
        g_invwn[r1] = 1.0f / fmaxf(sqrtf(s1), 1e-12f);
    }
}

// ---------------- kernel 3 (post-gemm): zero counts / touched sum rows -----
__global__ void k_zero_counts() {
    int i = blockIdx.x * blockDim.x + threadIdx.x;
    if (i < NC) g_counts[i] = 0.0f;          // NOTE: g_pos NOT touched (gemm wrote it)
}
__global__ void k_zero_sums() {
    int lab = g_lab[blockIdx.x];
    g_sums[(size_t)lab * DIM + threadIdx.x] = 0.0f;
}

// ---------------- kernel 4: persistent fp16 mma GEMM + fused softmax -------
// 296 CTAs (one wave, 2/SM). by = cta&7 is CONSTANT per CTA (296 % 8 == 0):
// A tile staged ONCE and reused across all ~21 class chunks. B flows through
// a 3-slot chunk ring prefetched 2 chunks ahead -> load latency hidden across
// tile boundaries. Per-tile math identical to the R14 champion.
#define P36   36                      // smem pitch (u32) -> 144 B rows
#define STG   (128 * P36 * 4)         // one matrix chunk: 18432 B
#define OFF_A    0                    // 2 chunks: A0 at 0, A1 at STG
#define OFF_B    (2 * STG)            // 3 ring slots
#define OFF_RED  (5 * STG)            // 92160, 4KB
#define OFF_INVS (OFF_RED + 4096)
#define OFF_LABS (OFF_INVS + 512)
#define SMEM_SZ  (OFF_LABS + 512)     // 97280 B; x2 CTAs <= 228KB/SM

__global__ void __launch_bounds__(256, 2)
k_gemm() {
    extern __shared__ char smem[];
    const uint32_t sb = smem_u32(smem);
    float* invs  = (float*)(smem + OFF_INVS);
    int*   labs  = (int*)(smem + OFF_LABS);
    float* red_m = (float*)(smem + OFF_RED);   // [128][4]
    float* red_s = red_m + 512;

    const int tid  = threadIdx.x;
    const int w    = tid >> 5, lane = tid & 31;
    const int q    = lane >> 2, qt = lane & 3;
    const int wm   = w >> 2, wn = w & 3;       // 2 x 4 warp grid
    const int cta  = blockIdx.x;
    const int by   = cta & 7;                  // constant batch tile
    const int bxb  = cta >> 3;                 // bx = bxb + 37*tileIdx
    const int b0   = by * 128;
    const int ntiles  = (NTILES - cta + GRID - 1) / GRID;
    const int nchunks = 2 * ntiles;

    if (tid < 128) labs[tid] = g_lab[b0 + tid];

    // ---- stage A once: both K-chunks of this CTA's 128 batch rows ----------
    #pragma unroll
    for (int kc = 0; kc < 2; kc++) {
        uint32_t ao = sb + OFF_A + kc * STG;
        #pragma unroll
        for (int it = 0; it < 4; it++) {
            int j = it * 256 + tid;
            int r = j >> 3, gq = j & 7;
            CP16(ao + r * 144 + gq * 16,
                 (const void*)(g_fnr + (size_t)(b0 + r) * DIM + kc * 64 + gq * 8));
        }
    }
    CP_COMMIT();

    // ---- B chunk prefetch into ring slot k%3 -------------------------------
    auto prefetch_chunk = [&](int k) {
        uint32_t bo = sb + OFF_B + (k % 3) * STG;
        int c0k = (bxb + 37 * (k >> 1)) * 128;
        int kc  = k & 1;
        #pragma unroll
        for (int it = 0; it < 4; it++) {
            int j = it * 256 + tid;
            int r = j >> 3, gq = j & 7;
            int c = c0k + r;
            if (c > NC - 1) c = NC - 1;        // clamp: finite, masked later
            CP16(bo + r * 144 + gq * 16,
                 (const void*)(g_wr + (size_t)c * DIM + kc * 64 + gq * 8));
        }
    };
    prefetch_chunk(0); CP_COMMIT();
    prefetch_chunk(1); CP_COMMIT();

    float acc[4][4][4];
    auto zero_acc = [&]() {
        #pragma unroll
        for (int i = 0; i < 4; i++)
            #pragma unroll
            for (int j = 0; j < 4; j++)
                #pragma unroll
                for (int x = 0; x < 4; x++) acc[i][j][x] = 0.0f;
    };

    auto mma_chunk = [&](uint32_t a_off, uint32_t b_off) {
        const uint32_t* As = (const uint32_t*)(smem + a_off);
        const uint32_t* Bs = (const uint32_t*)(smem + b_off);
        const uint32_t* Ab = &As[(wm * 64 + q) * P36 + qt];
        const uint32_t* Bb = &Bs[(wn * 32 + q) * P36 + qt];
        #pragma unroll
        for (int s = 0; s < 4; s++) {          // 4 k16-steps per chunk
            uint32_t a[4][4], b[4][2];
            #pragma unroll
            for (int i = 0; i < 4; i++) {
                const uint32_t* p = Ab + i * 16 * P36 + s * 8;
                a[i][0] = p[0];
                a[i][1] = p[8 * P36];
                a[i][2] = p[4];
                a[i][3] = p[8 * P36 + 4];
            }
            #pragma unroll
            for (int j = 0; j < 4; j++) {
                const uint32_t* p = Bb + j * 8 * P36 + s * 8;
                b[j][0] = p[0];
                b[j][1] = p[4];
            }
            #pragma unroll
            for (int i = 0; i < 4; i++)
                #pragma unroll
                for (int j = 0; j < 4; j++)
                    mma16(acc[i][j], a[i], b[j]);
        }
    };

    zero_acc();
    for (int g = 0; g < nchunks; g++) {
        const int  tileI = g >> 1;
        const int  bx    = bxb + 37 * tileI;
        const int  c0    = bx * 128;
        CP_WAIT(1);                      // chunk g (and A) complete; g+1 may fly
        __syncthreads();
        mma_chunk(OFF_A + (g & 1) * STG, OFF_B + (g % 3) * STG);
        if (!(g & 1)) {
            // invs for this tile: prev epilogue finished (program order + its sync)
            if (tid < 128) {
                int c = c0 + tid;
                invs[tid] = (c < NC) ? g_invwn[c] * SCALE : 0.0f;
            }
        }
        __syncthreads();                 // reads of slot g%3 + invs writes ordered
        if (g + 2 < nchunks) prefetch_chunk(g + 2);
        CP_COMMIT();                     // empty commit at tail is legal

        if (g & 1) {
            // ---- epilogue for tile tileI ----
            #pragma unroll
            for (int i = 0; i < 4; i++) {
                #pragma unroll
                for (int h = 0; h < 2; h++) {
                    int rloc = wm * 64 + i * 16 + q + h * 8;
                    int lab  = labs[rloc];
                    float vals[8];
                    int   cols[8];
                    float m = -INFINITY;
                    #pragma unroll
                    for (int j = 0; j < 4; j++) {
                        #pragma unroll
                        for (int cc = 0; cc < 2; cc++) {
                            int cl = wn * 32 + j * 8 + 2 * qt + cc;
                            int c  = c0 + cl;
                            float v = acc[i][j][h * 2 + cc] * invs[cl];
                            vals[j * 2 + cc] = v;
                            cols[j * 2 + cc] = c;
                            if (c == lab) g_pos[b0 + rloc] = v;   // one writer
                            if (c < NC && c != lab) m = fmaxf(m, v);
                        }
                    }
                    m = fmaxf(m, __shfl_xor_sync(0xffffffffu, m, 1));
                    m = fmaxf(m, __shfl_xor_sync(0xffffffffu, m, 2));
                    float ssum = 0.0f;
                    #pragma unroll
                    for (int x = 0; x < 8; x++)
                        if (cols[x] < NC && cols[x] != lab) ssum += __expf(vals[x] - m);
                    ssum += __shfl_xor_sync(0xffffffffu, ssum, 1);
                    ssum += __shfl_xor_sync(0xffffffffu, ssum, 2);
                    if (qt == 0) {
                        red_m[rloc * 4 + wn] = m;
                        red_s[rloc * 4 + wn] = ssum;
                    }
                }
            }
            __syncthreads();
            if (tid < 128) {
                float M = red_m[tid * 4], S = red_s[tid * 4];
                #pragma unroll
                for (int x = 1; x < 4; x++) {
                    float m2 = red_m[tid * 4 + x], s2 = red_s[tid * 4 + x];
                    if (m2 > M)      { S = S * __expf(M - m2) + s2; M = m2; }
                    else if (s2 > 0) { S += s2 * __expf(m2 - M); }
                }
                size_t pi = (size_t)(b0 + tid) * NCH + bx;
                g_pm[pi] = M;
                g_ps[pi] = S;
            }
            __syncthreads();             // red reusable next tile
            zero_acc();
        }
    }
}

// ---------------- kernel 5: per-row logsumexp combine + softplus -----------
__global__ void k_lossrow() {
    const int b = blockIdx.x;
    const int t = threadIdx.x;
    float M = -INFINITY, L = 0.0f;
    for (int ch = t; ch < NCH; ch += 256) {
        float m = g_pm[(size_t)b * NCH + ch];
        float s = g_ps[(size_t)b * NCH + ch];
        if (s > 0.0f) {
            if (m > M) { L = L * expf(M - m) + s; M = m; }
            else       { L += s * expf(m - M); }
        }
    }
    __shared__ float sm[256], ss[256];
    sm[t] = M; ss[t] = L;
    __syncthreads();
    for (int st = 128; st; st >>= 1) {
        if (t < st) {
            float m2 = sm[t + st], s2 = ss[t + st];
            float M1 = sm[t],      L1 = ss[t];
            if (s2 > 0.0f) {
                if (m2 > M1) { L1 = L1 * expf(M1 - m2) + s2; M1 = m2; }
                else         { L1 += s2 * expf(m2 - M1); }
            }
            sm[t] = M1; ss[t] = L1;
        }
        __syncthreads();
    }
    if (t == 0) {
        double lse = (double)sm[0] + log((double)ss[0]);
        double x = (double)MARGIN + lse - (double)g_pos[b];
        g_lossb[b] = (x > 0.0) ? (x + log1p(exp(-x))) : log1p(exp(x));
    }
}

// ---------------- kernel 6: deterministic mean -----------------------------
__global__ void k_losssum(float* __restrict__ out) {
    __shared__ double sm[1024];
    int t = threadIdx.x;
    sm[t] = g_lossb[t];
    __syncthreads();
    for (int st = 512; st; st >>= 1) {
        if (t < st) sm[t] += sm[t + st];
        __syncthreads();
    }
    if (t == 0) out[0] = (float)(sm[0] * (1.0 / 1024.0));
}

// ---------------- kernel 7/8: segment scatter + final blend ----------------
__global__ void k_accum() {
    int b   = blockIdx.x;
    int lab = g_lab[b];
    atomicAdd(&g_sums[(size_t)lab * DIM + threadIdx.x], g_fn[b * DIM + threadIdx.x]);
    if (threadIdx.x == 0) atomicAdd(&g_counts[lab], 1.0f);
}
__global__ void k_final(const float* __restrict__ weight, float* __restrict__ out) {
    size_t i = (size_t)blockIdx.x * 256 + threadIdx.x;
    int c = (int)(i >> 7);
    float cnt = g_counts[c];       // warp-uniform branch: one load path per warp
    float r;
    if (cnt > 0.0f) r = g_sums[i] / cnt;
    else            r = weight[i];
    out[1 + i] = r;
}

// ---------------- launch ---------------------------------------------------
extern "C" void kernel_launch(void* const* d_in, const int* in_sizes, int n_in,
                              void* d_out, int out_size) {
    const float* input  = nullptr;
    const int*   labraw = nullptr;
    const float* weight = nullptr;
    for (int i = 0; i < n_in; i++) {
        if      (in_sizes[i] == BSZ * DIM) input  = (const float*)d_in[i];
        else if (in_sizes[i] == BSZ)       labraw = (const int*)d_in[i];
        else if (in_sizes[i] == NC * DIM)  weight = (const float*)d_in[i];
    }
    float* out = (float*)d_out;

    cudaFuncSetAttribute(k_gemm, cudaFuncAttributeMaxDynamicSharedMemorySize, SMEM_SZ);

    k_cvt        <<<1,    1024>>>(labraw);
    k_norm_fn    <<<128,   256>>>(input);
    k_invwn      <<<6250,  256>>>(weight);
    k_gemm       <<<GRID,  256, SMEM_SZ>>>();     // launch index 3: ncu target
    k_zero_counts<<<391,   256>>>();
    k_zero_sums  <<<1024,  128>>>();
    k_lossrow    <<<1024,  256>>>();
    k_losssum    <<<1,    1024>>>(out);
    k_accum      <<<1024,  128>>>();
    k_final      <<<50000, 256>>>(weight, out);
}